// round 1
// baseline (speedup 1.0000x reference)
#include <cuda_runtime.h>
#include <cfloat>
#include <cstdint>

#define Bz 4
#define NN0 8192
#define NN1 2048
#define NN2 512
#define NN3 128

// ---------------- scratch (allocation-free) ----------------
__device__ int   g_idx0[Bz*NN1*16];
__device__ int   g_idx1[Bz*NN2*16];
__device__ int   g_idx2[Bz*NN3*16];
__device__ int   g_uidx0[Bz*NN2*3];
__device__ float g_ud20 [Bz*NN2*3];
__device__ int   g_uidx1[Bz*NN1*3];
__device__ float g_ud21 [Bz*NN1*3];
__device__ int   g_uidx2[Bz*NN0*3];
__device__ float g_ud22 [Bz*NN0*3];
__device__ float g_x1 [Bz*NN1*128];
__device__ float g_x2 [Bz*NN2*256];
__device__ float g_x3 [Bz*NN3*512];
__device__ float g_up0[Bz*NN2*256];
__device__ float g_up1[Bz*NN1*128];

// ---------------- brute force KNN ----------------
// one block per (query, batch); dist array in dynamic shared
template<int KK>
__global__ void knn_kernel(const float* __restrict__ qpos, const float* __restrict__ rpos,
                           int Nq, int Nr, int qbs, int rbs,
                           int* __restrict__ oidx, float* __restrict__ od2) {
    extern __shared__ float dist[];          // Nr floats
    __shared__ float wval[8];
    __shared__ int   widx[8];
    int b = blockIdx.y, q = blockIdx.x;
    const float* qp = qpos + ((size_t)b*qbs + q)*3;
    float qx = qp[0], qy = qp[1], qz = qp[2];
    float qq = qx*qx + qy*qy + qz*qz;
    const float* rp = rpos + (size_t)b*rbs*3;
    for (int r = threadIdx.x; r < Nr; r += blockDim.x) {
        float rx = rp[3*r+0], ry = rp[3*r+1], rz = rp[3*r+2];
        float rr = rx*rx + ry*ry + rz*rz;
        float dt = qx*rx + qy*ry + qz*rz;
        dist[r] = qq + rr - 2.0f*dt;         // same expanded form as reference
    }
    __syncthreads();
    int lane = threadIdx.x & 31, warp = threadIdx.x >> 5;
    int nwarp = blockDim.x >> 5;
    size_t obase = ((size_t)b*Nq + q)*KK;
    for (int s = 0; s < KK; s++) {
        float best = FLT_MAX; int bi = 0x7fffffff;
        for (int r = threadIdx.x; r < Nr; r += blockDim.x) {
            float dv = dist[r];
            if (dv < best) { best = dv; bi = r; }
        }
        #pragma unroll
        for (int off = 16; off > 0; off >>= 1) {
            float ov = __shfl_down_sync(0xffffffffu, best, off);
            int   oi = __shfl_down_sync(0xffffffffu, bi,   off);
            if (ov < best || (ov == best && oi < bi)) { best = ov; bi = oi; }
        }
        if (lane == 0) { wval[warp] = best; widx[warp] = bi; }
        __syncthreads();
        if (threadIdx.x == 0) {
            float bv = wval[0]; int bbi = widx[0];
            for (int w = 1; w < nwarp; w++) {
                float ov = wval[w]; int oi = widx[w];
                if (ov < bv || (ov == bv && oi < bbi)) { bv = ov; bbi = oi; }
            }
            oidx[obase + s] = bbi;
            if (od2) od2[obase + s] = fmaxf(bv, 0.0f);
            dist[bbi] = FLT_MAX;
        }
        __syncthreads();
    }
}

// ---------------- down: gather + 2-layer MLP + max over 16 neighbors ----------------
// one block per center, C_HID threads. feat & hidden stored transposed [d][k].
template<int C_PREV, int C_HID>
__global__ void down_kernel(const float* __restrict__ xprev, const float* __restrict__ pos,
                            const int* __restrict__ idx,
                            const float* __restrict__ W1, const float* __restrict__ b1,
                            const float* __restrict__ W2, const float* __restrict__ b2,
                            float* __restrict__ xout,
                            int Nq, int Nr, int pbs, int xbs) {
    constexpr int CIN = 3 + C_PREV;
    extern __shared__ float sm[];
    float* featT = sm;                 // CIN*16
    float* hT    = sm + CIN*16;       // C_HID*16
    __shared__ int nbs[16];
    int b = blockIdx.y, q = blockIdx.x;
    if (threadIdx.x < 16) nbs[threadIdx.x] = idx[((size_t)b*Nq + q)*16 + threadIdx.x];
    __syncthreads();
    const float* rp = pos + (size_t)b*pbs*3;
    float cx = rp[3*q+0], cy = rp[3*q+1], cz = rp[3*q+2];
    const float* xp = xprev + (size_t)b*xbs;
    for (int e = threadIdx.x; e < 16*CIN; e += blockDim.x) {
        int d = e >> 4, k = e & 15;
        int nb = nbs[k];
        float v;
        if      (d == 0) v = rp[3*nb+0] - cx;
        else if (d == 1) v = rp[3*nb+1] - cy;
        else if (d == 2) v = rp[3*nb+2] - cz;
        else             v = xp[(size_t)nb*C_PREV + (d-3)];
        featT[d*16 + k] = v;
    }
    __syncthreads();
    int j = threadIdx.x;
    float acc[16];
    {
        float bj = b1[j];
        #pragma unroll
        for (int k = 0; k < 16; k++) acc[k] = bj;
    }
    for (int d = 0; d < CIN; d++) {
        float w = W1[d*C_HID + j];
        const float4* f4 = reinterpret_cast<const float4*>(featT + d*16);
        #pragma unroll
        for (int k4 = 0; k4 < 4; k4++) {
            float4 f = f4[k4];
            acc[4*k4+0] = fmaf(f.x, w, acc[4*k4+0]);
            acc[4*k4+1] = fmaf(f.y, w, acc[4*k4+1]);
            acc[4*k4+2] = fmaf(f.z, w, acc[4*k4+2]);
            acc[4*k4+3] = fmaf(f.w, w, acc[4*k4+3]);
        }
    }
    {
        float4* hj = reinterpret_cast<float4*>(hT + j*16);
        #pragma unroll
        for (int k4 = 0; k4 < 4; k4++) {
            float4 h;
            h.x = fmaxf(acc[4*k4+0], 0.f);
            h.y = fmaxf(acc[4*k4+1], 0.f);
            h.z = fmaxf(acc[4*k4+2], 0.f);
            h.w = fmaxf(acc[4*k4+3], 0.f);
            hj[k4] = h;
        }
    }
    __syncthreads();
    {
        float bj = b2[j];
        #pragma unroll
        for (int k = 0; k < 16; k++) acc[k] = bj;
    }
    for (int jj = 0; jj < C_HID; jj++) {
        float w = W2[jj*C_HID + j];
        const float4* h4 = reinterpret_cast<const float4*>(hT + jj*16);
        #pragma unroll
        for (int k4 = 0; k4 < 4; k4++) {
            float4 f = h4[k4];
            acc[4*k4+0] = fmaf(f.x, w, acc[4*k4+0]);
            acc[4*k4+1] = fmaf(f.y, w, acc[4*k4+1]);
            acc[4*k4+2] = fmaf(f.z, w, acc[4*k4+2]);
            acc[4*k4+3] = fmaf(f.w, w, acc[4*k4+3]);
        }
    }
    float m = acc[0];
    #pragma unroll
    for (int k = 1; k < 16; k++) m = fmaxf(m, acc[k]);
    xout[((size_t)b*Nq + q)*C_HID + j] = m;
}

// ---------------- up: 3-NN inverse-distance interp + cat + linear + relu ----------------
template<int C_XC, int C_PRV, int C_OUT, int QT>
__global__ void up_kernel(const float* __restrict__ xc, const float* __restrict__ prv,
                          const int* __restrict__ idx, const float* __restrict__ d2,
                          const float* __restrict__ W, const float* __restrict__ bias,
                          float* __restrict__ out, int Nq, int Nc) {
    constexpr int CIN = C_XC + C_PRV;
    extern __shared__ float sm[];
    float* featT = sm;                 // CIN * QT, [d][q]
    __shared__ float wsh[QT][3];
    __shared__ int   ish[QT][3];
    int b = blockIdx.y;
    int q0 = blockIdx.x * QT;
    if (threadIdx.x < QT) {
        int q = q0 + threadIdx.x;
        size_t base = ((size_t)b*Nq + q)*3;
        float w0 = 1.0f/(d2[base+0] + 1e-8f);
        float w1 = 1.0f/(d2[base+1] + 1e-8f);
        float w2 = 1.0f/(d2[base+2] + 1e-8f);
        float s = w0 + w1 + w2;
        wsh[threadIdx.x][0] = w0/s; wsh[threadIdx.x][1] = w1/s; wsh[threadIdx.x][2] = w2/s;
        ish[threadIdx.x][0] = idx[base+0]; ish[threadIdx.x][1] = idx[base+1]; ish[threadIdx.x][2] = idx[base+2];
    }
    __syncthreads();
    const float* xcb = xc + (size_t)b*Nc*C_XC;
    for (int e = threadIdx.x; e < CIN*QT; e += blockDim.x) {
        int d = e / QT, qq = e % QT;
        float v;
        if (d < C_XC) {
            v = wsh[qq][0]*xcb[(size_t)ish[qq][0]*C_XC + d]
              + wsh[qq][1]*xcb[(size_t)ish[qq][1]*C_XC + d]
              + wsh[qq][2]*xcb[(size_t)ish[qq][2]*C_XC + d];
        } else {
            v = prv[((size_t)b*Nq + q0 + qq)*C_PRV + (d - C_XC)];
        }
        featT[e] = v;
    }
    __syncthreads();
    int j = threadIdx.x;
    float acc[QT];
    {
        float bj = bias[j];
        #pragma unroll
        for (int qq = 0; qq < QT; qq++) acc[qq] = bj;
    }
    for (int d = 0; d < CIN; d++) {
        float w = W[d*C_OUT + j];
        const float4* f4 = reinterpret_cast<const float4*>(featT + d*QT);
        #pragma unroll
        for (int q4 = 0; q4 < QT/4; q4++) {
            float4 f = f4[q4];
            acc[4*q4+0] = fmaf(f.x, w, acc[4*q4+0]);
            acc[4*q4+1] = fmaf(f.y, w, acc[4*q4+1]);
            acc[4*q4+2] = fmaf(f.z, w, acc[4*q4+2]);
            acc[4*q4+3] = fmaf(f.w, w, acc[4*q4+3]);
        }
    }
    #pragma unroll
    for (int qq = 0; qq < QT; qq++)
        out[((size_t)b*Nq + q0 + qq)*C_OUT + j] = fmaxf(acc[qq], 0.f);
}

// ---------------- fused: up2 (interp+cat+linear+relu) + final MLP (relu-linear-linear) ----------------
__global__ void up2_final_kernel(const float* __restrict__ up1,
                                 const float* __restrict__ x0, const float* __restrict__ pos0,
                                 const int* __restrict__ idx, const float* __restrict__ d2,
                                 const float* __restrict__ u2W, const float* __restrict__ u2b,
                                 const float* __restrict__ fW1, const float* __restrict__ fb1,
                                 const float* __restrict__ fW2, const float* __restrict__ fb2,
                                 float* __restrict__ out) {
    constexpr int QT = 8;
    __shared__ float featT[134*QT];
    __shared__ float h1T[128*QT];
    __shared__ float wsh[QT][3];
    __shared__ int   ish[QT][3];
    int b = blockIdx.y;
    int q0 = blockIdx.x * QT;
    if (threadIdx.x < QT) {
        int q = q0 + threadIdx.x;
        size_t base = ((size_t)b*NN0 + q)*3;
        float w0 = 1.0f/(d2[base+0] + 1e-8f);
        float w1 = 1.0f/(d2[base+1] + 1e-8f);
        float w2 = 1.0f/(d2[base+2] + 1e-8f);
        float s = w0 + w1 + w2;
        wsh[threadIdx.x][0] = w0/s; wsh[threadIdx.x][1] = w1/s; wsh[threadIdx.x][2] = w2/s;
        ish[threadIdx.x][0] = idx[base+0]; ish[threadIdx.x][1] = idx[base+1]; ish[threadIdx.x][2] = idx[base+2];
    }
    __syncthreads();
    const float* xcb = up1 + (size_t)b*NN1*128;
    for (int e = threadIdx.x; e < 134*QT; e += 128) {
        int d = e / QT, qq = e % QT;
        float v;
        if (d < 128) {
            v = wsh[qq][0]*xcb[(size_t)ish[qq][0]*128 + d]
              + wsh[qq][1]*xcb[(size_t)ish[qq][1]*128 + d]
              + wsh[qq][2]*xcb[(size_t)ish[qq][2]*128 + d];
        } else if (d < 131) {
            v = x0  [((size_t)b*NN0 + q0 + qq)*3 + (d-128)];
        } else {
            v = pos0[((size_t)b*NN0 + q0 + qq)*3 + (d-131)];
        }
        featT[e] = v;
    }
    __syncthreads();
    int j = threadIdx.x;
    float acc[QT];
    // stage u2
    {
        float bj = u2b[j];
        #pragma unroll
        for (int qq = 0; qq < QT; qq++) acc[qq] = bj;
    }
    for (int d = 0; d < 134; d++) {
        float w = u2W[d*128 + j];
        const float4* f4 = reinterpret_cast<const float4*>(featT + d*QT);
        #pragma unroll
        for (int q4 = 0; q4 < 2; q4++) {
            float4 f = f4[q4];
            acc[4*q4+0] = fmaf(f.x, w, acc[4*q4+0]);
            acc[4*q4+1] = fmaf(f.y, w, acc[4*q4+1]);
            acc[4*q4+2] = fmaf(f.z, w, acc[4*q4+2]);
            acc[4*q4+3] = fmaf(f.w, w, acc[4*q4+3]);
        }
    }
    #pragma unroll
    for (int qq = 0; qq < QT; qq++) h1T[j*QT + qq] = fmaxf(acc[qq], 0.f);
    __syncthreads();
    // stage f1
    {
        float bj = fb1[j];
        #pragma unroll
        for (int qq = 0; qq < QT; qq++) acc[qq] = bj;
    }
    for (int jj = 0; jj < 128; jj++) {
        float w = fW1[jj*128 + j];
        const float4* f4 = reinterpret_cast<const float4*>(h1T + jj*QT);
        #pragma unroll
        for (int q4 = 0; q4 < 2; q4++) {
            float4 f = f4[q4];
            acc[4*q4+0] = fmaf(f.x, w, acc[4*q4+0]);
            acc[4*q4+1] = fmaf(f.y, w, acc[4*q4+1]);
            acc[4*q4+2] = fmaf(f.z, w, acc[4*q4+2]);
            acc[4*q4+3] = fmaf(f.w, w, acc[4*q4+3]);
        }
    }
    #pragma unroll
    for (int qq = 0; qq < QT; qq++) featT[j*QT + qq] = fmaxf(acc[qq], 0.f);  // reuse featT as h2
    __syncthreads();
    // stage f2 (no relu)
    {
        float bj = fb2[j];
        #pragma unroll
        for (int qq = 0; qq < QT; qq++) acc[qq] = bj;
    }
    for (int jj = 0; jj < 128; jj++) {
        float w = fW2[jj*128 + j];
        const float4* f4 = reinterpret_cast<const float4*>(featT + jj*QT);
        #pragma unroll
        for (int q4 = 0; q4 < 2; q4++) {
            float4 f = f4[q4];
            acc[4*q4+0] = fmaf(f.x, w, acc[4*q4+0]);
            acc[4*q4+1] = fmaf(f.y, w, acc[4*q4+1]);
            acc[4*q4+2] = fmaf(f.z, w, acc[4*q4+2]);
            acc[4*q4+3] = fmaf(f.w, w, acc[4*q4+3]);
        }
    }
    #pragma unroll
    for (int qq = 0; qq < QT; qq++)
        out[((size_t)b*NN0 + q0 + qq)*128 + j] = acc[qq];
}

// ---------------- host launch ----------------
extern "C" void kernel_launch(void* const* d_in, const int* in_sizes, int n_in,
                              void* d_out, int out_size) {
    const float* x    = (const float*)d_in[0];
    const float* pos  = (const float*)d_in[1];
    const float* d0W1 = (const float*)d_in[2];
    const float* d0b1 = (const float*)d_in[3];
    const float* d0W2 = (const float*)d_in[4];
    const float* d0b2 = (const float*)d_in[5];
    const float* d1W1 = (const float*)d_in[6];
    const float* d1b1 = (const float*)d_in[7];
    const float* d1W2 = (const float*)d_in[8];
    const float* d1b2 = (const float*)d_in[9];
    const float* d2W1 = (const float*)d_in[10];
    const float* d2b1 = (const float*)d_in[11];
    const float* d2W2 = (const float*)d_in[12];
    const float* d2b2 = (const float*)d_in[13];
    const float* u0W  = (const float*)d_in[14];
    const float* u0b  = (const float*)d_in[15];
    const float* u1W  = (const float*)d_in[16];
    const float* u1b  = (const float*)d_in[17];
    const float* u2W  = (const float*)d_in[18];
    const float* u2b  = (const float*)d_in[19];
    const float* fW1  = (const float*)d_in[20];
    const float* fb1  = (const float*)d_in[21];
    const float* fW2  = (const float*)d_in[22];
    const float* fb2  = (const float*)d_in[23];
    float* out = (float*)d_out;

    int *idx0, *idx1, *idx2, *uidx0, *uidx1, *uidx2;
    float *ud20, *ud21, *ud22, *x1, *x2, *x3, *up0, *up1;
    cudaGetSymbolAddress((void**)&idx0,  g_idx0);
    cudaGetSymbolAddress((void**)&idx1,  g_idx1);
    cudaGetSymbolAddress((void**)&idx2,  g_idx2);
    cudaGetSymbolAddress((void**)&uidx0, g_uidx0);
    cudaGetSymbolAddress((void**)&uidx1, g_uidx1);
    cudaGetSymbolAddress((void**)&uidx2, g_uidx2);
    cudaGetSymbolAddress((void**)&ud20,  g_ud20);
    cudaGetSymbolAddress((void**)&ud21,  g_ud21);
    cudaGetSymbolAddress((void**)&ud22,  g_ud22);
    cudaGetSymbolAddress((void**)&x1,    g_x1);
    cudaGetSymbolAddress((void**)&x2,    g_x2);
    cudaGetSymbolAddress((void**)&x3,    g_x3);
    cudaGetSymbolAddress((void**)&up0,   g_up0);
    cudaGetSymbolAddress((void**)&up1,   g_up1);

    // opt-in for the 49.3KB dynamic-shared instantiation (idempotent host call)
    cudaFuncSetAttribute((const void*)down_kernel<256,512>,
                         cudaFuncAttributeMaxDynamicSharedMemorySize, 56*1024);

    // ---- down 0 ----
    knn_kernel<16><<<dim3(NN1,Bz), 256, NN0*sizeof(float)>>>(pos, pos, NN1, NN0, NN0, NN0, idx0, nullptr);
    down_kernel<3,128><<<dim3(NN1,Bz), 128, (6*16 + 128*16)*sizeof(float)>>>(
        x, pos, idx0, d0W1,d0b1,d0W2,d0b2, x1, NN1, NN0, NN0, NN0*3);
    // ---- down 1 ----
    knn_kernel<16><<<dim3(NN2,Bz), 256, NN1*sizeof(float)>>>(pos, pos, NN2, NN1, NN0, NN0, idx1, nullptr);
    down_kernel<128,256><<<dim3(NN2,Bz), 256, (131*16 + 256*16)*sizeof(float)>>>(
        x1, pos, idx1, d1W1,d1b1,d1W2,d1b2, x2, NN2, NN1, NN0, NN1*128);
    // ---- down 2 ----
    knn_kernel<16><<<dim3(NN3,Bz), 256, NN2*sizeof(float)>>>(pos, pos, NN3, NN2, NN0, NN0, idx2, nullptr);
    down_kernel<256,512><<<dim3(NN3,Bz), 512, (259*16 + 512*16)*sizeof(float)>>>(
        x2, pos, idx2, d2W1,d2b1,d2W2,d2b2, x3, NN3, NN2, NN0, NN2*256);
    // ---- up 0: queries pos2(512) over refs pos3(128) ----
    knn_kernel<3><<<dim3(NN2,Bz), 256, NN3*sizeof(float)>>>(pos, pos, NN2, NN3, NN0, NN0, uidx0, ud20);
    up_kernel<512,256,256,4><<<dim3(NN2/4,Bz), 256, 768*4*sizeof(float)>>>(
        x3, x2, uidx0, ud20, u0W, u0b, up0, NN2, NN3);
    // ---- up 1: queries pos1(2048) over refs pos2(512) ----
    knn_kernel<3><<<dim3(NN1,Bz), 256, NN2*sizeof(float)>>>(pos, pos, NN1, NN2, NN0, NN0, uidx1, ud21);
    up_kernel<256,128,128,8><<<dim3(NN1/8,Bz), 128, 384*8*sizeof(float)>>>(
        up0, x1, uidx1, ud21, u1W, u1b, up1, NN1, NN2);
    // ---- up 2 + final MLP (fused): queries pos0(8192) over refs pos1(2048) ----
    knn_kernel<3><<<dim3(NN0,Bz), 256, NN1*sizeof(float)>>>(pos, pos, NN0, NN1, NN0, NN0, uidx2, ud22);
    up2_final_kernel<<<dim3(NN0/8,Bz), 128>>>(up1, x, pos, uidx2, ud22,
                                              u2W,u2b, fW1,fb1, fW2,fb2, out);
    // ---- second tuple element: pos0 passthrough ----
    if (out_size >= Bz*NN0*128 + Bz*NN0*3) {
        cudaMemcpyAsync(out + (size_t)Bz*NN0*128, pos,
                        (size_t)Bz*NN0*3*sizeof(float), cudaMemcpyDeviceToDevice);
    }
}

// round 2
// speedup vs baseline: 1.0702x; 1.0702x over previous
#include <cuda_runtime.h>
#include <cfloat>
#include <cstdint>

#define Bz 4
#define NN0 8192
#define NN1 2048
#define NN2 512
#define NN3 128

typedef unsigned long long u64;

__device__ __forceinline__ u64 pack2(float x, float y) {
    u64 r; asm("mov.b64 %0, {%1, %2};" : "=l"(r) : "f"(x), "f"(y)); return r;
}
__device__ __forceinline__ float2 unpack2(u64 v) {
    float2 r; asm("mov.b64 {%0, %1}, %2;" : "=f"(r.x), "=f"(r.y) : "l"(v)); return r;
}
__device__ __forceinline__ u64 ffma2(u64 a, u64 b, u64 c) {
    u64 d; asm("fma.rn.f32x2 %0, %1, %2, %3;" : "=l"(d) : "l"(a), "l"(b), "l"(c)); return d;
}

// ---------------- scratch (allocation-free) ----------------
__device__ int   g_idx0[Bz*NN1*16];
__device__ int   g_idx1[Bz*NN2*16];
__device__ int   g_idx2[Bz*NN3*16];
__device__ int   g_uidx0[Bz*NN2*3];
__device__ float g_ud20 [Bz*NN2*3];
__device__ int   g_uidx1[Bz*NN1*3];
__device__ float g_ud21 [Bz*NN1*3];
__device__ int   g_uidx2[Bz*NN0*3];
__device__ float g_ud22 [Bz*NN0*3];
__device__ float g_x1 [Bz*NN1*128];
__device__ float g_x2 [Bz*NN2*256];
__device__ float g_x3 [Bz*NN3*512];
__device__ float g_up0[Bz*NN2*256];
__device__ float g_up1[Bz*NN1*128];

// ---------------- brute force KNN ----------------
template<int KK>
__global__ void knn_kernel(const float* __restrict__ qpos, const float* __restrict__ rpos,
                           int Nq, int Nr, int qbs, int rbs,
                           int* __restrict__ oidx, float* __restrict__ od2) {
    extern __shared__ float dist[];          // Nr floats
    __shared__ float wval[8];
    __shared__ int   widx[8];
    int b = blockIdx.y, q = blockIdx.x;
    const float* qp = qpos + ((size_t)b*qbs + q)*3;
    float qx = qp[0], qy = qp[1], qz = qp[2];
    float qq = qx*qx + qy*qy + qz*qz;
    const float* rp = rpos + (size_t)b*rbs*3;
    for (int r = threadIdx.x; r < Nr; r += blockDim.x) {
        float rx = rp[3*r+0], ry = rp[3*r+1], rz = rp[3*r+2];
        float rr = rx*rx + ry*ry + rz*rz;
        float dt = qx*rx + qy*ry + qz*rz;
        dist[r] = qq + rr - 2.0f*dt;         // same expanded form as reference
    }
    __syncthreads();
    int lane = threadIdx.x & 31, warp = threadIdx.x >> 5;
    int nwarp = blockDim.x >> 5;
    size_t obase = ((size_t)b*Nq + q)*KK;
    for (int s = 0; s < KK; s++) {
        float best = FLT_MAX; int bi = 0x7fffffff;
        for (int r = threadIdx.x; r < Nr; r += blockDim.x) {
            float dv = dist[r];
            if (dv < best) { best = dv; bi = r; }
        }
        #pragma unroll
        for (int off = 16; off > 0; off >>= 1) {
            float ov = __shfl_down_sync(0xffffffffu, best, off);
            int   oi = __shfl_down_sync(0xffffffffu, bi,   off);
            if (ov < best || (ov == best && oi < bi)) { best = ov; bi = oi; }
        }
        if (lane == 0) { wval[warp] = best; widx[warp] = bi; }
        __syncthreads();
        if (threadIdx.x == 0) {
            float bv = wval[0]; int bbi = widx[0];
            for (int w = 1; w < nwarp; w++) {
                float ov = wval[w]; int oi = widx[w];
                if (ov < bv || (ov == bv && oi < bbi)) { bv = ov; bbi = oi; }
            }
            oidx[obase + s] = bbi;
            if (od2) od2[obase + s] = fmaxf(bv, 0.0f);
            dist[bbi] = FLT_MAX;
        }
        __syncthreads();
    }
}

// ---------------- down: gather + 2-layer MLP + max over 16 neighbors ----------------
// one block per center, C_HID/2 threads; each thread owns 2 adjacent output channels.
// feat & hidden transposed [d][k], k=16 neighbors, packed f32x2 over k.
template<int C_PREV, int C_HID>
__global__ void down_kernel(const float* __restrict__ xprev, const float* __restrict__ pos,
                            const int* __restrict__ idx,
                            const float* __restrict__ W1, const float* __restrict__ b1,
                            const float* __restrict__ W2, const float* __restrict__ b2,
                            float* __restrict__ xout,
                            int Nq, int Nr, int pbs, int xbs) {
    constexpr int CIN = 3 + C_PREV;
    extern __shared__ float sm[];
    float* featT = sm;               // CIN*16
    float* hT    = sm + CIN*16;      // C_HID*16
    __shared__ int nbs[16];
    int b = blockIdx.y, q = blockIdx.x;
    if (threadIdx.x < 16) nbs[threadIdx.x] = idx[((size_t)b*Nq + q)*16 + threadIdx.x];
    __syncthreads();
    const float* rp = pos + (size_t)b*pbs*3;
    float cx = rp[3*q+0], cy = rp[3*q+1], cz = rp[3*q+2];
    const float* xp = xprev + (size_t)b*xbs;
    for (int e = threadIdx.x; e < 16*CIN; e += blockDim.x) {
        int d = e >> 4, k = e & 15;
        int nb = nbs[k];
        float v;
        if      (d == 0) v = rp[3*nb+0] - cx;
        else if (d == 1) v = rp[3*nb+1] - cy;
        else if (d == 2) v = rp[3*nb+2] - cz;
        else             v = xp[(size_t)nb*C_PREV + (d-3)];
        featT[d*16 + k] = v;
    }
    __syncthreads();
    int j0 = 2*threadIdx.x;
    u64 a0[8], a1[8];
    // ---- layer 1 ----
    {
        float2 bb = *reinterpret_cast<const float2*>(&b1[j0]);
        u64 p0 = pack2(bb.x, bb.x), p1 = pack2(bb.y, bb.y);
        #pragma unroll
        for (int i = 0; i < 8; i++) { a0[i] = p0; a1[i] = p1; }
    }
    for (int d = 0; d < CIN; d++) {
        float2 w = *reinterpret_cast<const float2*>(&W1[d*C_HID + j0]);
        u64 w0 = pack2(w.x, w.x), w1 = pack2(w.y, w.y);
        const ulonglong2* f = reinterpret_cast<const ulonglong2*>(featT + d*16);
        #pragma unroll
        for (int i = 0; i < 4; i++) {
            ulonglong2 fv = f[i];
            a0[2*i+0] = ffma2(fv.x, w0, a0[2*i+0]);
            a0[2*i+1] = ffma2(fv.y, w0, a0[2*i+1]);
            a1[2*i+0] = ffma2(fv.x, w1, a1[2*i+0]);
            a1[2*i+1] = ffma2(fv.y, w1, a1[2*i+1]);
        }
    }
    {
        float4* h0 = reinterpret_cast<float4*>(hT + (size_t)j0*16);
        float4* h1 = reinterpret_cast<float4*>(hT + (size_t)(j0+1)*16);
        #pragma unroll
        for (int i = 0; i < 4; i++) {
            float2 x0 = unpack2(a0[2*i]), x1 = unpack2(a0[2*i+1]);
            h0[i] = make_float4(fmaxf(x0.x,0.f), fmaxf(x0.y,0.f), fmaxf(x1.x,0.f), fmaxf(x1.y,0.f));
            float2 y0 = unpack2(a1[2*i]), y1 = unpack2(a1[2*i+1]);
            h1[i] = make_float4(fmaxf(y0.x,0.f), fmaxf(y0.y,0.f), fmaxf(y1.x,0.f), fmaxf(y1.y,0.f));
        }
    }
    __syncthreads();
    // ---- layer 2 ----
    {
        float2 bb = *reinterpret_cast<const float2*>(&b2[j0]);
        u64 p0 = pack2(bb.x, bb.x), p1 = pack2(bb.y, bb.y);
        #pragma unroll
        for (int i = 0; i < 8; i++) { a0[i] = p0; a1[i] = p1; }
    }
    for (int d = 0; d < C_HID; d++) {
        float2 w = *reinterpret_cast<const float2*>(&W2[d*C_HID + j0]);
        u64 w0 = pack2(w.x, w.x), w1 = pack2(w.y, w.y);
        const ulonglong2* f = reinterpret_cast<const ulonglong2*>(hT + d*16);
        #pragma unroll
        for (int i = 0; i < 4; i++) {
            ulonglong2 fv = f[i];
            a0[2*i+0] = ffma2(fv.x, w0, a0[2*i+0]);
            a0[2*i+1] = ffma2(fv.y, w0, a0[2*i+1]);
            a1[2*i+0] = ffma2(fv.x, w1, a1[2*i+0]);
            a1[2*i+1] = ffma2(fv.y, w1, a1[2*i+1]);
        }
    }
    // ---- max pool over 16 neighbors ----
    float m0 = -FLT_MAX, m1 = -FLT_MAX;
    #pragma unroll
    for (int i = 0; i < 8; i++) {
        float2 x = unpack2(a0[i]); m0 = fmaxf(m0, fmaxf(x.x, x.y));
        float2 y = unpack2(a1[i]); m1 = fmaxf(m1, fmaxf(y.x, y.y));
    }
    *reinterpret_cast<float2*>(&xout[((size_t)b*Nq + q)*C_HID + j0]) = make_float2(m0, m1);
}

// ---------------- up: 3-NN inverse-distance interp + cat + linear + relu ----------------
// QT=16 queries per block, C_OUT/2 threads, 2 adjacent channels per thread, f32x2 over q.
template<int C_XC, int C_PRV, int C_OUT>
__global__ void up_kernel(const float* __restrict__ xc, const float* __restrict__ prv,
                          const int* __restrict__ idx, const float* __restrict__ d2,
                          const float* __restrict__ W, const float* __restrict__ bias,
                          float* __restrict__ out, int Nq, int Nc) {
    constexpr int CIN = C_XC + C_PRV;
    constexpr int QT = 16;
    extern __shared__ float sm[];
    float* featT = sm;               // CIN * 16, [d][q]
    __shared__ float wsh[QT][3];
    __shared__ int   ish[QT][3];
    int b = blockIdx.y;
    int q0 = blockIdx.x * QT;
    if (threadIdx.x < QT) {
        int q = q0 + threadIdx.x;
        size_t base = ((size_t)b*Nq + q)*3;
        float w0 = 1.0f/(d2[base+0] + 1e-8f);
        float w1 = 1.0f/(d2[base+1] + 1e-8f);
        float w2 = 1.0f/(d2[base+2] + 1e-8f);
        float s = w0 + w1 + w2;
        wsh[threadIdx.x][0] = w0/s; wsh[threadIdx.x][1] = w1/s; wsh[threadIdx.x][2] = w2/s;
        ish[threadIdx.x][0] = idx[base+0]; ish[threadIdx.x][1] = idx[base+1]; ish[threadIdx.x][2] = idx[base+2];
    }
    __syncthreads();
    const float* xcb = xc + (size_t)b*Nc*C_XC;
    for (int e = threadIdx.x; e < CIN*QT; e += blockDim.x) {
        int d = e >> 4, qq = e & 15;
        float v;
        if (d < C_XC) {
            v = wsh[qq][0]*xcb[(size_t)ish[qq][0]*C_XC + d]
              + wsh[qq][1]*xcb[(size_t)ish[qq][1]*C_XC + d]
              + wsh[qq][2]*xcb[(size_t)ish[qq][2]*C_XC + d];
        } else {
            v = prv[((size_t)b*Nq + q0 + qq)*C_PRV + (d - C_XC)];
        }
        featT[e] = v;
    }
    __syncthreads();
    int j0 = 2*threadIdx.x;
    u64 a0[8], a1[8];
    {
        float2 bb = *reinterpret_cast<const float2*>(&bias[j0]);
        u64 p0 = pack2(bb.x, bb.x), p1 = pack2(bb.y, bb.y);
        #pragma unroll
        for (int i = 0; i < 8; i++) { a0[i] = p0; a1[i] = p1; }
    }
    for (int d = 0; d < CIN; d++) {
        float2 w = *reinterpret_cast<const float2*>(&W[d*C_OUT + j0]);
        u64 w0 = pack2(w.x, w.x), w1 = pack2(w.y, w.y);
        const ulonglong2* f = reinterpret_cast<const ulonglong2*>(featT + d*QT);
        #pragma unroll
        for (int i = 0; i < 4; i++) {
            ulonglong2 fv = f[i];
            a0[2*i+0] = ffma2(fv.x, w0, a0[2*i+0]);
            a0[2*i+1] = ffma2(fv.y, w0, a0[2*i+1]);
            a1[2*i+0] = ffma2(fv.x, w1, a1[2*i+0]);
            a1[2*i+1] = ffma2(fv.y, w1, a1[2*i+1]);
        }
    }
    size_t obase = ((size_t)b*Nq + q0)*C_OUT + j0;
    #pragma unroll
    for (int i = 0; i < 8; i++) {
        float2 x = unpack2(a0[i]), y = unpack2(a1[i]);
        *reinterpret_cast<float2*>(&out[obase + (size_t)(2*i+0)*C_OUT]) =
            make_float2(fmaxf(x.x,0.f), fmaxf(y.x,0.f));
        *reinterpret_cast<float2*>(&out[obase + (size_t)(2*i+1)*C_OUT]) =
            make_float2(fmaxf(x.y,0.f), fmaxf(y.y,0.f));
    }
}

// ---------------- fused: up2 + final MLP (relu-linear-relu-linear) ----------------
// QT=16, 64 threads, 2 adjacent channels per thread.
__global__ void up2_final_kernel(const float* __restrict__ up1,
                                 const float* __restrict__ x0, const float* __restrict__ pos0,
                                 const int* __restrict__ idx, const float* __restrict__ d2,
                                 const float* __restrict__ u2W, const float* __restrict__ u2b,
                                 const float* __restrict__ fW1, const float* __restrict__ fb1,
                                 const float* __restrict__ fW2, const float* __restrict__ fb2,
                                 float* __restrict__ out) {
    constexpr int QT = 16;
    __shared__ float featT[134*QT];
    __shared__ float h1T[128*QT];
    __shared__ float wsh[QT][3];
    __shared__ int   ish[QT][3];
    int b = blockIdx.y;
    int q0 = blockIdx.x * QT;
    if (threadIdx.x < QT) {
        int q = q0 + threadIdx.x;
        size_t base = ((size_t)b*NN0 + q)*3;
        float w0 = 1.0f/(d2[base+0] + 1e-8f);
        float w1 = 1.0f/(d2[base+1] + 1e-8f);
        float w2 = 1.0f/(d2[base+2] + 1e-8f);
        float s = w0 + w1 + w2;
        wsh[threadIdx.x][0] = w0/s; wsh[threadIdx.x][1] = w1/s; wsh[threadIdx.x][2] = w2/s;
        ish[threadIdx.x][0] = idx[base+0]; ish[threadIdx.x][1] = idx[base+1]; ish[threadIdx.x][2] = idx[base+2];
    }
    __syncthreads();
    const float* xcb = up1 + (size_t)b*NN1*128;
    for (int e = threadIdx.x; e < 134*QT; e += 64) {
        int d = e >> 4, qq = e & 15;
        float v;
        if (d < 128) {
            v = wsh[qq][0]*xcb[(size_t)ish[qq][0]*128 + d]
              + wsh[qq][1]*xcb[(size_t)ish[qq][1]*128 + d]
              + wsh[qq][2]*xcb[(size_t)ish[qq][2]*128 + d];
        } else if (d < 131) {
            v = x0  [((size_t)b*NN0 + q0 + qq)*3 + (d-128)];
        } else {
            v = pos0[((size_t)b*NN0 + q0 + qq)*3 + (d-131)];
        }
        featT[e] = v;
    }
    __syncthreads();
    int j0 = 2*threadIdx.x;
    u64 a0[8], a1[8];

    // ---- stage u2: [134] -> 128, relu ----
    {
        float2 bb = *reinterpret_cast<const float2*>(&u2b[j0]);
        u64 p0 = pack2(bb.x, bb.x), p1 = pack2(bb.y, bb.y);
        #pragma unroll
        for (int i = 0; i < 8; i++) { a0[i] = p0; a1[i] = p1; }
    }
    for (int d = 0; d < 134; d++) {
        float2 w = *reinterpret_cast<const float2*>(&u2W[d*128 + j0]);
        u64 w0 = pack2(w.x, w.x), w1 = pack2(w.y, w.y);
        const ulonglong2* f = reinterpret_cast<const ulonglong2*>(featT + d*QT);
        #pragma unroll
        for (int i = 0; i < 4; i++) {
            ulonglong2 fv = f[i];
            a0[2*i+0] = ffma2(fv.x, w0, a0[2*i+0]);
            a0[2*i+1] = ffma2(fv.y, w0, a0[2*i+1]);
            a1[2*i+0] = ffma2(fv.x, w1, a1[2*i+0]);
            a1[2*i+1] = ffma2(fv.y, w1, a1[2*i+1]);
        }
    }
    {
        float4* h0 = reinterpret_cast<float4*>(h1T + (size_t)j0*QT);
        float4* h1 = reinterpret_cast<float4*>(h1T + (size_t)(j0+1)*QT);
        #pragma unroll
        for (int i = 0; i < 4; i++) {
            float2 x0v = unpack2(a0[2*i]), x1v = unpack2(a0[2*i+1]);
            h0[i] = make_float4(fmaxf(x0v.x,0.f), fmaxf(x0v.y,0.f), fmaxf(x1v.x,0.f), fmaxf(x1v.y,0.f));
            float2 y0v = unpack2(a1[2*i]), y1v = unpack2(a1[2*i+1]);
            h1[i] = make_float4(fmaxf(y0v.x,0.f), fmaxf(y0v.y,0.f), fmaxf(y1v.x,0.f), fmaxf(y1v.y,0.f));
        }
    }
    __syncthreads();

    // ---- stage f1: 128 -> 128, relu (result into featT) ----
    {
        float2 bb = *reinterpret_cast<const float2*>(&fb1[j0]);
        u64 p0 = pack2(bb.x, bb.x), p1 = pack2(bb.y, bb.y);
        #pragma unroll
        for (int i = 0; i < 8; i++) { a0[i] = p0; a1[i] = p1; }
    }
    for (int d = 0; d < 128; d++) {
        float2 w = *reinterpret_cast<const float2*>(&fW1[d*128 + j0]);
        u64 w0 = pack2(w.x, w.x), w1 = pack2(w.y, w.y);
        const ulonglong2* f = reinterpret_cast<const ulonglong2*>(h1T + d*QT);
        #pragma unroll
        for (int i = 0; i < 4; i++) {
            ulonglong2 fv = f[i];
            a0[2*i+0] = ffma2(fv.x, w0, a0[2*i+0]);
            a0[2*i+1] = ffma2(fv.y, w0, a0[2*i+1]);
            a1[2*i+0] = ffma2(fv.x, w1, a1[2*i+0]);
            a1[2*i+1] = ffma2(fv.y, w1, a1[2*i+1]);
        }
    }
    __syncthreads();   // h1T reads done before featT overwrite? featT distinct; but keep ordering for f2 reads of featT
    {
        float4* h0 = reinterpret_cast<float4*>(featT + (size_t)j0*QT);
        float4* h1 = reinterpret_cast<float4*>(featT + (size_t)(j0+1)*QT);
        #pragma unroll
        for (int i = 0; i < 4; i++) {
            float2 x0v = unpack2(a0[2*i]), x1v = unpack2(a0[2*i+1]);
            h0[i] = make_float4(fmaxf(x0v.x,0.f), fmaxf(x0v.y,0.f), fmaxf(x1v.x,0.f), fmaxf(x1v.y,0.f));
            float2 y0v = unpack2(a1[2*i]), y1v = unpack2(a1[2*i+1]);
            h1[i] = make_float4(fmaxf(y0v.x,0.f), fmaxf(y0v.y,0.f), fmaxf(y1v.x,0.f), fmaxf(y1v.y,0.f));
        }
    }
    __syncthreads();

    // ---- stage f2: 128 -> 128, no relu ----
    {
        float2 bb = *reinterpret_cast<const float2*>(&fb2[j0]);
        u64 p0 = pack2(bb.x, bb.x), p1 = pack2(bb.y, bb.y);
        #pragma unroll
        for (int i = 0; i < 8; i++) { a0[i] = p0; a1[i] = p1; }
    }
    for (int d = 0; d < 128; d++) {
        float2 w = *reinterpret_cast<const float2*>(&fW2[d*128 + j0]);
        u64 w0 = pack2(w.x, w.x), w1 = pack2(w.y, w.y);
        const ulonglong2* f = reinterpret_cast<const ulonglong2*>(featT + d*QT);
        #pragma unroll
        for (int i = 0; i < 4; i++) {
            ulonglong2 fv = f[i];
            a0[2*i+0] = ffma2(fv.x, w0, a0[2*i+0]);
            a0[2*i+1] = ffma2(fv.y, w0, a0[2*i+1]);
            a1[2*i+0] = ffma2(fv.x, w1, a1[2*i+0]);
            a1[2*i+1] = ffma2(fv.y, w1, a1[2*i+1]);
        }
    }
    size_t obase = ((size_t)b*NN0 + q0)*128 + j0;
    #pragma unroll
    for (int i = 0; i < 8; i++) {
        float2 x = unpack2(a0[i]), y = unpack2(a1[i]);
        *reinterpret_cast<float2*>(&out[obase + (size_t)(2*i+0)*128]) = make_float2(x.x, y.x);
        *reinterpret_cast<float2*>(&out[obase + (size_t)(2*i+1)*128]) = make_float2(x.y, y.y);
    }
}

// ---------------- host launch ----------------
extern "C" void kernel_launch(void* const* d_in, const int* in_sizes, int n_in,
                              void* d_out, int out_size) {
    const float* x    = (const float*)d_in[0];
    const float* pos  = (const float*)d_in[1];
    const float* d0W1 = (const float*)d_in[2];
    const float* d0b1 = (const float*)d_in[3];
    const float* d0W2 = (const float*)d_in[4];
    const float* d0b2 = (const float*)d_in[5];
    const float* d1W1 = (const float*)d_in[6];
    const float* d1b1 = (const float*)d_in[7];
    const float* d1W2 = (const float*)d_in[8];
    const float* d1b2 = (const float*)d_in[9];
    const float* d2W1 = (const float*)d_in[10];
    const float* d2b1 = (const float*)d_in[11];
    const float* d2W2 = (const float*)d_in[12];
    const float* d2b2 = (const float*)d_in[13];
    const float* u0W  = (const float*)d_in[14];
    const float* u0b  = (const float*)d_in[15];
    const float* u1W  = (const float*)d_in[16];
    const float* u1b  = (const float*)d_in[17];
    const float* u2W  = (const float*)d_in[18];
    const float* u2b  = (const float*)d_in[19];
    const float* fW1  = (const float*)d_in[20];
    const float* fb1  = (const float*)d_in[21];
    const float* fW2  = (const float*)d_in[22];
    const float* fb2  = (const float*)d_in[23];
    float* out = (float*)d_out;

    int *idx0, *idx1, *idx2, *uidx0, *uidx1, *uidx2;
    float *ud20, *ud21, *ud22, *x1, *x2, *x3, *up0, *up1;
    cudaGetSymbolAddress((void**)&idx0,  g_idx0);
    cudaGetSymbolAddress((void**)&idx1,  g_idx1);
    cudaGetSymbolAddress((void**)&idx2,  g_idx2);
    cudaGetSymbolAddress((void**)&uidx0, g_uidx0);
    cudaGetSymbolAddress((void**)&uidx1, g_uidx1);
    cudaGetSymbolAddress((void**)&uidx2, g_uidx2);
    cudaGetSymbolAddress((void**)&ud20,  g_ud20);
    cudaGetSymbolAddress((void**)&ud21,  g_ud21);
    cudaGetSymbolAddress((void**)&ud22,  g_ud22);
    cudaGetSymbolAddress((void**)&x1,    g_x1);
    cudaGetSymbolAddress((void**)&x2,    g_x2);
    cudaGetSymbolAddress((void**)&x3,    g_x3);
    cudaGetSymbolAddress((void**)&up0,   g_up0);
    cudaGetSymbolAddress((void**)&up1,   g_up1);

    // opt-in for large dynamic shared instantiations (idempotent host calls)
    cudaFuncSetAttribute((const void*)down_kernel<256,512>,
                         cudaFuncAttributeMaxDynamicSharedMemorySize, 56*1024);
    cudaFuncSetAttribute((const void*)up_kernel<512,256,256>,
                         cudaFuncAttributeMaxDynamicSharedMemorySize, 50*1024);

    // ---- down 0 ----
    knn_kernel<16><<<dim3(NN1,Bz), 256, NN0*sizeof(float)>>>(pos, pos, NN1, NN0, NN0, NN0, idx0, nullptr);
    down_kernel<3,128><<<dim3(NN1,Bz), 64, (6*16 + 128*16)*sizeof(float)>>>(
        x, pos, idx0, d0W1,d0b1,d0W2,d0b2, x1, NN1, NN0, NN0, NN0*3);
    // ---- down 1 ----
    knn_kernel<16><<<dim3(NN2,Bz), 256, NN1*sizeof(float)>>>(pos, pos, NN2, NN1, NN0, NN0, idx1, nullptr);
    down_kernel<128,256><<<dim3(NN2,Bz), 128, (131*16 + 256*16)*sizeof(float)>>>(
        x1, pos, idx1, d1W1,d1b1,d1W2,d1b2, x2, NN2, NN1, NN0, NN1*128);
    // ---- down 2 ----
    knn_kernel<16><<<dim3(NN3,Bz), 256, NN2*sizeof(float)>>>(pos, pos, NN3, NN2, NN0, NN0, idx2, nullptr);
    down_kernel<256,512><<<dim3(NN3,Bz), 256, (259*16 + 512*16)*sizeof(float)>>>(
        x2, pos, idx2, d2W1,d2b1,d2W2,d2b2, x3, NN3, NN2, NN0, NN2*256);
    // ---- up 0: queries pos2(512) over refs pos3(128) ----
    knn_kernel<3><<<dim3(NN2,Bz), 256, NN3*sizeof(float)>>>(pos, pos, NN2, NN3, NN0, NN0, uidx0, ud20);
    up_kernel<512,256,256><<<dim3(NN2/16,Bz), 128, 768*16*sizeof(float)>>>(
        x3, x2, uidx0, ud20, u0W, u0b, up0, NN2, NN3);
    // ---- up 1: queries pos1(2048) over refs pos2(512) ----
    knn_kernel<3><<<dim3(NN1,Bz), 256, NN2*sizeof(float)>>>(pos, pos, NN1, NN2, NN0, NN0, uidx1, ud21);
    up_kernel<256,128,128><<<dim3(NN1/16,Bz), 64, 384*16*sizeof(float)>>>(
        up0, x1, uidx1, ud21, u1W, u1b, up1, NN1, NN2);
    // ---- up 2 + final MLP (fused): queries pos0(8192) over refs pos1(2048) ----
    knn_kernel<3><<<dim3(NN0,Bz), 256, NN1*sizeof(float)>>>(pos, pos, NN0, NN1, NN0, NN0, uidx2, ud22);
    up2_final_kernel<<<dim3(NN0/16,Bz), 64>>>(up1, x, pos, uidx2, ud22,
                                              u2W,u2b, fW1,fb1, fW2,fb2, out);
    // ---- second tuple element: pos0 passthrough ----
    if (out_size >= Bz*NN0*128 + Bz*NN0*3) {
        cudaMemcpyAsync(out + (size_t)Bz*NN0*128, pos,
                        (size_t)Bz*NN0*3*sizeof(float), cudaMemcpyDeviceToDevice);
    }
}

// round 3
// speedup vs baseline: 1.1275x; 1.0535x over previous
#include <cuda_runtime.h>
#include <cfloat>
#include <cstdint>

#define Bz 4
#define NN0 8192
#define NN1 2048
#define NN2 512
#define NN3 128

typedef unsigned long long u64;

__device__ __forceinline__ u64 pack2(float x, float y) {
    u64 r; asm("mov.b64 %0, {%1, %2};" : "=l"(r) : "f"(x), "f"(y)); return r;
}
__device__ __forceinline__ float2 unpack2(u64 v) {
    float2 r; asm("mov.b64 {%0, %1}, %2;" : "=f"(r.x), "=f"(r.y) : "l"(v)); return r;
}
__device__ __forceinline__ u64 ffma2(u64 a, u64 b, u64 c) {
    u64 d; asm("fma.rn.f32x2 %0, %1, %2, %3;" : "=l"(d) : "l"(a), "l"(b), "l"(c)); return d;
}
__device__ __forceinline__ unsigned ordf(float f) {
    unsigned b = __float_as_uint(f);
    return b ^ (((unsigned)((int)b >> 31)) | 0x80000000u);
}
__device__ __forceinline__ float unordf(unsigned m) {
    unsigned b = m ^ ((m & 0x80000000u) ? 0x80000000u : 0xffffffffu);
    return __uint_as_float(b);
}

// ---------------- scratch (allocation-free) ----------------
__device__ int   g_idx0[Bz*NN1*16];
__device__ int   g_idx1[Bz*NN2*16];
__device__ int   g_idx2[Bz*NN3*16];
__device__ int   g_uidx0[Bz*NN2*3];
__device__ float g_ud20 [Bz*NN2*3];
__device__ int   g_uidx1[Bz*NN1*3];
__device__ float g_ud21 [Bz*NN1*3];
__device__ int   g_uidx2[Bz*NN0*3];
__device__ float g_ud22 [Bz*NN0*3];
__device__ float g_x1 [Bz*NN1*128];
__device__ float g_x2 [Bz*NN2*256];
__device__ float g_x3 [Bz*NN3*512];
__device__ float g_up0[Bz*NN2*256];
__device__ float g_up1[Bz*NN1*128];
__device__ __align__(16) float g_wdup[2*806656];

// segment offsets (elements) of the 11 weight matrices in the packed dup buffer
#define OFF_D0W1 0
#define OFF_D0W2 768
#define OFF_D1W1 17152
#define OFF_D1W2 50688
#define OFF_D2W1 116224
#define OFF_D2W2 248832
#define OFF_U0W  510976
#define OFF_U1W  707584
#define OFF_U2W  756736
#define OFF_FW1  773888
#define OFF_FW2  790272
#define W_TOTAL  806656

// ---------------- weight duplication prep ----------------
__global__ void dup_weights_kernel(const float* __restrict__ s0, const float* __restrict__ s1,
                                   const float* __restrict__ s2, const float* __restrict__ s3,
                                   const float* __restrict__ s4, const float* __restrict__ s5,
                                   const float* __restrict__ s6, const float* __restrict__ s7,
                                   const float* __restrict__ s8, const float* __restrict__ s9,
                                   const float* __restrict__ s10, float* __restrict__ dst) {
    int gid = blockIdx.x*256 + threadIdx.x;
    if (gid >= W_TOTAL) return;
    const int offs[11] = {OFF_D0W1,OFF_D0W2,OFF_D1W1,OFF_D1W2,OFF_D2W1,OFF_D2W2,
                          OFF_U0W,OFF_U1W,OFF_U2W,OFF_FW1,OFF_FW2};
    const float* srcs[11] = {s0,s1,s2,s3,s4,s5,s6,s7,s8,s9,s10};
    int seg = 0;
    #pragma unroll
    for (int i = 1; i < 11; i++) seg = (gid >= offs[i]) ? i : seg;
    float v = srcs[seg][gid - offs[seg]];
    reinterpret_cast<float2*>(dst)[gid] = make_float2(v, v);
}

// ---------------- KNN: register-resident chunks + redux argmin ----------------
// 256 threads per block; thread t owns refs {t, t+256, ...}. Exact argmin with
// tie -> lower index via packed u64 key (ordered-float bits << 32 | idx).
template<int KK, int CNT>
__global__ void knn_kernel(const float* __restrict__ qpos, const float* __restrict__ rpos,
                           int Nq, int Nr, int* __restrict__ oidx, float* __restrict__ od2) {
    __shared__ u64 wkey[8];
    int b = blockIdx.y, q = blockIdx.x;
    int tid = threadIdx.x;
    const float* qp = qpos + ((size_t)b*NN0 + q)*3;
    float qx = qp[0], qy = qp[1], qz = qp[2];
    float qq = qx*qx + qy*qy + qz*qz;
    const float* rp = rpos + (size_t)b*NN0*3;

    float dist[CNT];
    u64 lkey = ~0ull;
    #pragma unroll
    for (int i = 0; i < CNT; i++) {
        int r = tid + 256*i;
        float dv = FLT_MAX;
        if (CNT > 1 || r < Nr) {
            float rx = rp[3*r+0], ry = rp[3*r+1], rz = rp[3*r+2];
            float rr = rx*rx + ry*ry + rz*rz;
            float dt = qx*rx + qy*ry + qz*rz;
            dv = qq + rr - 2.0f*dt;
        }
        dist[i] = dv;
        u64 k = ((u64)ordf(dv) << 32) | (unsigned)r;
        if (k < lkey) lkey = k;
    }

    size_t obase = ((size_t)b*Nq + q)*KK;
    for (int s = 0; s < KK; s++) {
        unsigned hi = (unsigned)(lkey >> 32);
        unsigned mh = __reduce_min_sync(0xffffffffu, hi);
        unsigned lo = (hi == mh) ? (unsigned)lkey : 0xffffffffu;
        unsigned ml = __reduce_min_sync(0xffffffffu, lo);
        if ((tid & 31) == 0) wkey[tid >> 5] = ((u64)mh << 32) | ml;
        __syncthreads();
        u64 best = wkey[0];
        #pragma unroll
        for (int w = 1; w < 8; w++) { u64 k = wkey[w]; if (k < best) best = k; }
        if (tid == 0) {
            oidx[obase + s] = (int)(unsigned)best;
            if (od2) od2[obase + s] = fmaxf(unordf((unsigned)(best >> 32)), 0.0f);
        }
        if (s + 1 < KK) {
            int widx = (int)(unsigned)best;
            if ((widx & 255) == tid) {
                int slot = widx >> 8;
                #pragma unroll
                for (int i = 0; i < CNT; i++) if (i == slot) dist[i] = FLT_MAX;
                u64 nk = ~0ull;
                #pragma unroll
                for (int i = 0; i < CNT; i++) {
                    int r = tid + 256*i;
                    u64 k = ((u64)ordf(dist[i]) << 32) | (unsigned)r;
                    if (k < nk) nk = k;
                }
                lkey = nk;
            }
        }
        __syncthreads();   // protect wkey reuse next iteration
    }
}

// ---------------- down: gather + 2-layer MLP + max over 16 neighbors ----------------
// C_HID/2 threads per block (one center); dup weights -> LDG.128 per d, no packs.
template<int C_PREV, int C_HID>
__global__ void down_kernel(const float* __restrict__ xprev, const float* __restrict__ pos,
                            const int* __restrict__ idx,
                            const float* __restrict__ W1d, const float* __restrict__ b1,
                            const float* __restrict__ W2d, const float* __restrict__ b2,
                            float* __restrict__ xout, int Nq, int xbs) {
    constexpr int CIN = 3 + C_PREV;
    extern __shared__ float sm[];
    float* featT = sm;               // CIN*16
    float* hT    = sm + CIN*16;      // C_HID*16
    __shared__ int nbs[16];
    int b = blockIdx.y, q = blockIdx.x;
    if (threadIdx.x < 16) nbs[threadIdx.x] = idx[((size_t)b*Nq + q)*16 + threadIdx.x];
    __syncthreads();
    const float* rp = pos + (size_t)b*NN0*3;
    float cx = rp[3*q+0], cy = rp[3*q+1], cz = rp[3*q+2];
    const float* xp = xprev + (size_t)b*xbs;
    for (int e = threadIdx.x; e < 16*CIN; e += blockDim.x) {
        int d = e >> 4, k = e & 15;
        int nb = nbs[k];
        float v;
        if      (d == 0) v = rp[3*nb+0] - cx;
        else if (d == 1) v = rp[3*nb+1] - cy;
        else if (d == 2) v = rp[3*nb+2] - cz;
        else             v = xp[(size_t)nb*C_PREV + (d-3)];
        featT[d*16 + k] = v;
    }
    __syncthreads();
    int j0 = 2*threadIdx.x;
    u64 a0[8], a1[8];
    // ---- layer 1 ----
    {
        float2 bb = *reinterpret_cast<const float2*>(&b1[j0]);
        u64 p0 = pack2(bb.x, bb.x), p1 = pack2(bb.y, bb.y);
        #pragma unroll
        for (int i = 0; i < 8; i++) { a0[i] = p0; a1[i] = p1; }
    }
    #pragma unroll 2
    for (int d = 0; d < CIN; d++) {
        ulonglong2 w = *reinterpret_cast<const ulonglong2*>(W1d + 2*(d*C_HID + j0));
        const ulonglong2* f = reinterpret_cast<const ulonglong2*>(featT + d*16);
        ulonglong2 f0 = f[0], f1 = f[1], f2 = f[2], f3 = f[3];
        a0[0]=ffma2(f0.x,w.x,a0[0]); a0[1]=ffma2(f0.y,w.x,a0[1]);
        a0[2]=ffma2(f1.x,w.x,a0[2]); a0[3]=ffma2(f1.y,w.x,a0[3]);
        a0[4]=ffma2(f2.x,w.x,a0[4]); a0[5]=ffma2(f2.y,w.x,a0[5]);
        a0[6]=ffma2(f3.x,w.x,a0[6]); a0[7]=ffma2(f3.y,w.x,a0[7]);
        a1[0]=ffma2(f0.x,w.y,a1[0]); a1[1]=ffma2(f0.y,w.y,a1[1]);
        a1[2]=ffma2(f1.x,w.y,a1[2]); a1[3]=ffma2(f1.y,w.y,a1[3]);
        a1[4]=ffma2(f2.x,w.y,a1[4]); a1[5]=ffma2(f2.y,w.y,a1[5]);
        a1[6]=ffma2(f3.x,w.y,a1[6]); a1[7]=ffma2(f3.y,w.y,a1[7]);
    }
    {
        float4* h0 = reinterpret_cast<float4*>(hT + (size_t)j0*16);
        float4* h1 = reinterpret_cast<float4*>(hT + (size_t)(j0+1)*16);
        #pragma unroll
        for (int i = 0; i < 4; i++) {
            float2 x0 = unpack2(a0[2*i]), x1 = unpack2(a0[2*i+1]);
            h0[i] = make_float4(fmaxf(x0.x,0.f), fmaxf(x0.y,0.f), fmaxf(x1.x,0.f), fmaxf(x1.y,0.f));
            float2 y0 = unpack2(a1[2*i]), y1 = unpack2(a1[2*i+1]);
            h1[i] = make_float4(fmaxf(y0.x,0.f), fmaxf(y0.y,0.f), fmaxf(y1.x,0.f), fmaxf(y1.y,0.f));
        }
    }
    __syncthreads();
    // ---- layer 2 ----
    {
        float2 bb = *reinterpret_cast<const float2*>(&b2[j0]);
        u64 p0 = pack2(bb.x, bb.x), p1 = pack2(bb.y, bb.y);
        #pragma unroll
        for (int i = 0; i < 8; i++) { a0[i] = p0; a1[i] = p1; }
    }
    #pragma unroll 2
    for (int d = 0; d < C_HID; d++) {
        ulonglong2 w = *reinterpret_cast<const ulonglong2*>(W2d + 2*(d*C_HID + j0));
        const ulonglong2* f = reinterpret_cast<const ulonglong2*>(hT + d*16);
        ulonglong2 f0 = f[0], f1 = f[1], f2 = f[2], f3 = f[3];
        a0[0]=ffma2(f0.x,w.x,a0[0]); a0[1]=ffma2(f0.y,w.x,a0[1]);
        a0[2]=ffma2(f1.x,w.x,a0[2]); a0[3]=ffma2(f1.y,w.x,a0[3]);
        a0[4]=ffma2(f2.x,w.x,a0[4]); a0[5]=ffma2(f2.y,w.x,a0[5]);
        a0[6]=ffma2(f3.x,w.x,a0[6]); a0[7]=ffma2(f3.y,w.x,a0[7]);
        a1[0]=ffma2(f0.x,w.y,a1[0]); a1[1]=ffma2(f0.y,w.y,a1[1]);
        a1[2]=ffma2(f1.x,w.y,a1[2]); a1[3]=ffma2(f1.y,w.y,a1[3]);
        a1[4]=ffma2(f2.x,w.y,a1[4]); a1[5]=ffma2(f2.y,w.y,a1[5]);
        a1[6]=ffma2(f3.x,w.y,a1[6]); a1[7]=ffma2(f3.y,w.y,a1[7]);
    }
    // ---- max pool over 16 neighbors ----
    float m0 = -FLT_MAX, m1 = -FLT_MAX;
    #pragma unroll
    for (int i = 0; i < 8; i++) {
        float2 x = unpack2(a0[i]); m0 = fmaxf(m0, fmaxf(x.x, x.y));
        float2 y = unpack2(a1[i]); m1 = fmaxf(m1, fmaxf(y.x, y.y));
    }
    *reinterpret_cast<float2*>(&xout[((size_t)b*Nq + q)*C_HID + j0]) = make_float2(m0, m1);
}

// ---------------- up: 3-NN inverse-distance interp + cat + linear + relu ----------------
template<int C_XC, int C_PRV, int C_OUT>
__global__ void up_kernel(const float* __restrict__ xc, const float* __restrict__ prv,
                          const int* __restrict__ idx, const float* __restrict__ d2,
                          const float* __restrict__ Wd, const float* __restrict__ bias,
                          float* __restrict__ out, int Nq, int Nc) {
    constexpr int CIN = C_XC + C_PRV;
    constexpr int QT = 16;
    extern __shared__ float sm[];
    float* featT = sm;               // CIN * 16, [d][q]
    __shared__ float wsh[QT][3];
    __shared__ int   ish[QT][3];
    int b = blockIdx.y;
    int q0 = blockIdx.x * QT;
    if (threadIdx.x < QT) {
        int q = q0 + threadIdx.x;
        size_t base = ((size_t)b*Nq + q)*3;
        float w0 = 1.0f/(d2[base+0] + 1e-8f);
        float w1 = 1.0f/(d2[base+1] + 1e-8f);
        float w2 = 1.0f/(d2[base+2] + 1e-8f);
        float s = w0 + w1 + w2;
        wsh[threadIdx.x][0] = w0/s; wsh[threadIdx.x][1] = w1/s; wsh[threadIdx.x][2] = w2/s;
        ish[threadIdx.x][0] = idx[base+0]; ish[threadIdx.x][1] = idx[base+1]; ish[threadIdx.x][2] = idx[base+2];
    }
    __syncthreads();
    const float* xcb = xc + (size_t)b*Nc*C_XC;
    for (int e = threadIdx.x; e < CIN*QT; e += blockDim.x) {
        int d = e >> 4, qq = e & 15;
        float v;
        if (d < C_XC) {
            v = wsh[qq][0]*xcb[(size_t)ish[qq][0]*C_XC + d]
              + wsh[qq][1]*xcb[(size_t)ish[qq][1]*C_XC + d]
              + wsh[qq][2]*xcb[(size_t)ish[qq][2]*C_XC + d];
        } else {
            v = prv[((size_t)b*Nq + q0 + qq)*C_PRV + (d - C_XC)];
        }
        featT[e] = v;
    }
    __syncthreads();
    int j0 = 2*threadIdx.x;
    u64 a0[8], a1[8];
    {
        float2 bb = *reinterpret_cast<const float2*>(&bias[j0]);
        u64 p0 = pack2(bb.x, bb.x), p1 = pack2(bb.y, bb.y);
        #pragma unroll
        for (int i = 0; i < 8; i++) { a0[i] = p0; a1[i] = p1; }
    }
    #pragma unroll 2
    for (int d = 0; d < CIN; d++) {
        ulonglong2 w = *reinterpret_cast<const ulonglong2*>(Wd + 2*(d*C_OUT + j0));
        const ulonglong2* f = reinterpret_cast<const ulonglong2*>(featT + d*QT);
        ulonglong2 f0 = f[0], f1 = f[1], f2 = f[2], f3 = f[3];
        a0[0]=ffma2(f0.x,w.x,a0[0]); a0[1]=ffma2(f0.y,w.x,a0[1]);
        a0[2]=ffma2(f1.x,w.x,a0[2]); a0[3]=ffma2(f1.y,w.x,a0[3]);
        a0[4]=ffma2(f2.x,w.x,a0[4]); a0[5]=ffma2(f2.y,w.x,a0[5]);
        a0[6]=ffma2(f3.x,w.x,a0[6]); a0[7]=ffma2(f3.y,w.x,a0[7]);
        a1[0]=ffma2(f0.x,w.y,a1[0]); a1[1]=ffma2(f0.y,w.y,a1[1]);
        a1[2]=ffma2(f1.x,w.y,a1[2]); a1[3]=ffma2(f1.y,w.y,a1[3]);
        a1[4]=ffma2(f2.x,w.y,a1[4]); a1[5]=ffma2(f2.y,w.y,a1[5]);
        a1[6]=ffma2(f3.x,w.y,a1[6]); a1[7]=ffma2(f3.y,w.y,a1[7]);
    }
    size_t obase = ((size_t)b*Nq + q0)*C_OUT + j0;
    #pragma unroll
    for (int i = 0; i < 8; i++) {
        float2 x = unpack2(a0[i]), y = unpack2(a1[i]);
        *reinterpret_cast<float2*>(&out[obase + (size_t)(2*i+0)*C_OUT]) =
            make_float2(fmaxf(x.x,0.f), fmaxf(y.x,0.f));
        *reinterpret_cast<float2*>(&out[obase + (size_t)(2*i+1)*C_OUT]) =
            make_float2(fmaxf(x.y,0.f), fmaxf(y.y,0.f));
    }
}

// ---------------- fused: up2 + final MLP ----------------
__global__ void up2_final_kernel(const float* __restrict__ up1,
                                 const float* __restrict__ x0, const float* __restrict__ pos0,
                                 const int* __restrict__ idx, const float* __restrict__ d2,
                                 const float* __restrict__ u2Wd, const float* __restrict__ u2b,
                                 const float* __restrict__ fW1d, const float* __restrict__ fb1,
                                 const float* __restrict__ fW2d, const float* __restrict__ fb2,
                                 float* __restrict__ out) {
    constexpr int QT = 16;
    __shared__ float featT[134*QT];
    __shared__ float h1T[128*QT];
    __shared__ float wsh[QT][3];
    __shared__ int   ish[QT][3];
    int b = blockIdx.y;
    int q0 = blockIdx.x * QT;
    if (threadIdx.x < QT) {
        int q = q0 + threadIdx.x;
        size_t base = ((size_t)b*NN0 + q)*3;
        float w0 = 1.0f/(d2[base+0] + 1e-8f);
        float w1 = 1.0f/(d2[base+1] + 1e-8f);
        float w2 = 1.0f/(d2[base+2] + 1e-8f);
        float s = w0 + w1 + w2;
        wsh[threadIdx.x][0] = w0/s; wsh[threadIdx.x][1] = w1/s; wsh[threadIdx.x][2] = w2/s;
        ish[threadIdx.x][0] = idx[base+0]; ish[threadIdx.x][1] = idx[base+1]; ish[threadIdx.x][2] = idx[base+2];
    }
    __syncthreads();
    const float* xcb = up1 + (size_t)b*NN1*128;
    for (int e = threadIdx.x; e < 134*QT; e += 64) {
        int d = e >> 4, qq = e & 15;
        float v;
        if (d < 128) {
            v = wsh[qq][0]*xcb[(size_t)ish[qq][0]*128 + d]
              + wsh[qq][1]*xcb[(size_t)ish[qq][1]*128 + d]
              + wsh[qq][2]*xcb[(size_t)ish[qq][2]*128 + d];
        } else if (d < 131) {
            v = x0  [((size_t)b*NN0 + q0 + qq)*3 + (d-128)];
        } else {
            v = pos0[((size_t)b*NN0 + q0 + qq)*3 + (d-131)];
        }
        featT[e] = v;
    }
    __syncthreads();
    int j0 = 2*threadIdx.x;
    u64 a0[8], a1[8];

    // ---- stage u2: 134 -> 128, relu ----
    {
        float2 bb = *reinterpret_cast<const float2*>(&u2b[j0]);
        u64 p0 = pack2(bb.x, bb.x), p1 = pack2(bb.y, bb.y);
        #pragma unroll
        for (int i = 0; i < 8; i++) { a0[i] = p0; a1[i] = p1; }
    }
    #pragma unroll 2
    for (int d = 0; d < 134; d++) {
        ulonglong2 w = *reinterpret_cast<const ulonglong2*>(u2Wd + 2*(d*128 + j0));
        const ulonglong2* f = reinterpret_cast<const ulonglong2*>(featT + d*QT);
        ulonglong2 f0 = f[0], f1 = f[1], f2 = f[2], f3 = f[3];
        a0[0]=ffma2(f0.x,w.x,a0[0]); a0[1]=ffma2(f0.y,w.x,a0[1]);
        a0[2]=ffma2(f1.x,w.x,a0[2]); a0[3]=ffma2(f1.y,w.x,a0[3]);
        a0[4]=ffma2(f2.x,w.x,a0[4]); a0[5]=ffma2(f2.y,w.x,a0[5]);
        a0[6]=ffma2(f3.x,w.x,a0[6]); a0[7]=ffma2(f3.y,w.x,a0[7]);
        a1[0]=ffma2(f0.x,w.y,a1[0]); a1[1]=ffma2(f0.y,w.y,a1[1]);
        a1[2]=ffma2(f1.x,w.y,a1[2]); a1[3]=ffma2(f1.y,w.y,a1[3]);
        a1[4]=ffma2(f2.x,w.y,a1[4]); a1[5]=ffma2(f2.y,w.y,a1[5]);
        a1[6]=ffma2(f3.x,w.y,a1[6]); a1[7]=ffma2(f3.y,w.y,a1[7]);
    }
    {
        float4* h0 = reinterpret_cast<float4*>(h1T + (size_t)j0*QT);
        float4* h1 = reinterpret_cast<float4*>(h1T + (size_t)(j0+1)*QT);
        #pragma unroll
        for (int i = 0; i < 4; i++) {
            float2 x0v = unpack2(a0[2*i]), x1v = unpack2(a0[2*i+1]);
            h0[i] = make_float4(fmaxf(x0v.x,0.f), fmaxf(x0v.y,0.f), fmaxf(x1v.x,0.f), fmaxf(x1v.y,0.f));
            float2 y0v = unpack2(a1[2*i]), y1v = unpack2(a1[2*i+1]);
            h1[i] = make_float4(fmaxf(y0v.x,0.f), fmaxf(y0v.y,0.f), fmaxf(y1v.x,0.f), fmaxf(y1v.y,0.f));
        }
    }
    __syncthreads();

    // ---- stage f1: 128 -> 128, relu (into featT) ----
    {
        float2 bb = *reinterpret_cast<const float2*>(&fb1[j0]);
        u64 p0 = pack2(bb.x, bb.x), p1 = pack2(bb.y, bb.y);
        #pragma unroll
        for (int i = 0; i < 8; i++) { a0[i] = p0; a1[i] = p1; }
    }
    #pragma unroll 2
    for (int d = 0; d < 128; d++) {
        ulonglong2 w = *reinterpret_cast<const ulonglong2*>(fW1d + 2*(d*128 + j0));
        const ulonglong2* f = reinterpret_cast<const ulonglong2*>(h1T + d*QT);
        ulonglong2 f0 = f[0], f1 = f[1], f2 = f[2], f3 = f[3];
        a0[0]=ffma2(f0.x,w.x,a0[0]); a0[1]=ffma2(f0.y,w.x,a0[1]);
        a0[2]=ffma2(f1.x,w.x,a0[2]); a0[3]=ffma2(f1.y,w.x,a0[3]);
        a0[4]=ffma2(f2.x,w.x,a0[4]); a0[5]=ffma2(f2.y,w.x,a0[5]);
        a0[6]=ffma2(f3.x,w.x,a0[6]); a0[7]=ffma2(f3.y,w.x,a0[7]);
        a1[0]=ffma2(f0.x,w.y,a1[0]); a1[1]=ffma2(f0.y,w.y,a1[1]);
        a1[2]=ffma2(f1.x,w.y,a1[2]); a1[3]=ffma2(f1.y,w.y,a1[3]);
        a1[4]=ffma2(f2.x,w.y,a1[4]); a1[5]=ffma2(f2.y,w.y,a1[5]);
        a1[6]=ffma2(f3.x,w.y,a1[6]); a1[7]=ffma2(f3.y,w.y,a1[7]);
    }
    __syncthreads();
    {
        float4* h0 = reinterpret_cast<float4*>(featT + (size_t)j0*QT);
        float4* h1 = reinterpret_cast<float4*>(featT + (size_t)(j0+1)*QT);
        #pragma unroll
        for (int i = 0; i < 4; i++) {
            float2 x0v = unpack2(a0[2*i]), x1v = unpack2(a0[2*i+1]);
            h0[i] = make_float4(fmaxf(x0v.x,0.f), fmaxf(x0v.y,0.f), fmaxf(x1v.x,0.f), fmaxf(x1v.y,0.f));
            float2 y0v = unpack2(a1[2*i]), y1v = unpack2(a1[2*i+1]);
            h1[i] = make_float4(fmaxf(y0v.x,0.f), fmaxf(y0v.y,0.f), fmaxf(y1v.x,0.f), fmaxf(y1v.y,0.f));
        }
    }
    __syncthreads();

    // ---- stage f2: 128 -> 128, no relu ----
    {
        float2 bb = *reinterpret_cast<const float2*>(&fb2[j0]);
        u64 p0 = pack2(bb.x, bb.x), p1 = pack2(bb.y, bb.y);
        #pragma unroll
        for (int i = 0; i < 8; i++) { a0[i] = p0; a1[i] = p1; }
    }
    #pragma unroll 2
    for (int d = 0; d < 128; d++) {
        ulonglong2 w = *reinterpret_cast<const ulonglong2*>(fW2d + 2*(d*128 + j0));
        const ulonglong2* f = reinterpret_cast<const ulonglong2*>(featT + d*QT);
        ulonglong2 f0 = f[0], f1 = f[1], f2 = f[2], f3 = f[3];
        a0[0]=ffma2(f0.x,w.x,a0[0]); a0[1]=ffma2(f0.y,w.x,a0[1]);
        a0[2]=ffma2(f1.x,w.x,a0[2]); a0[3]=ffma2(f1.y,w.x,a0[3]);
        a0[4]=ffma2(f2.x,w.x,a0[4]); a0[5]=ffma2(f2.y,w.x,a0[5]);
        a0[6]=ffma2(f3.x,w.x,a0[6]); a0[7]=ffma2(f3.y,w.x,a0[7]);
        a1[0]=ffma2(f0.x,w.y,a1[0]); a1[1]=ffma2(f0.y,w.y,a1[1]);
        a1[2]=ffma2(f1.x,w.y,a1[2]); a1[3]=ffma2(f1.y,w.y,a1[3]);
        a1[4]=ffma2(f2.x,w.y,a1[4]); a1[5]=ffma2(f2.y,w.y,a1[5]);
        a1[6]=ffma2(f3.x,w.y,a1[6]); a1[7]=ffma2(f3.y,w.y,a1[7]);
    }
    size_t obase = ((size_t)b*NN0 + q0)*128 + j0;
    #pragma unroll
    for (int i = 0; i < 8; i++) {
        float2 x = unpack2(a0[i]), y = unpack2(a1[i]);
        *reinterpret_cast<float2*>(&out[obase + (size_t)(2*i+0)*128]) = make_float2(x.x, y.x);
        *reinterpret_cast<float2*>(&out[obase + (size_t)(2*i+1)*128]) = make_float2(x.y, y.y);
    }
}

// ---------------- host launch ----------------
extern "C" void kernel_launch(void* const* d_in, const int* in_sizes, int n_in,
                              void* d_out, int out_size) {
    const float* x    = (const float*)d_in[0];
    const float* pos  = (const float*)d_in[1];
    const float* d0W1 = (const float*)d_in[2];
    const float* d0b1 = (const float*)d_in[3];
    const float* d0W2 = (const float*)d_in[4];
    const float* d0b2 = (const float*)d_in[5];
    const float* d1W1 = (const float*)d_in[6];
    const float* d1b1 = (const float*)d_in[7];
    const float* d1W2 = (const float*)d_in[8];
    const float* d1b2 = (const float*)d_in[9];
    const float* d2W1 = (const float*)d_in[10];
    const float* d2b1 = (const float*)d_in[11];
    const float* d2W2 = (const float*)d_in[12];
    const float* d2b2 = (const float*)d_in[13];
    const float* u0W  = (const float*)d_in[14];
    const float* u0b  = (const float*)d_in[15];
    const float* u1W  = (const float*)d_in[16];
    const float* u1b  = (const float*)d_in[17];
    const float* u2W  = (const float*)d_in[18];
    const float* u2b  = (const float*)d_in[19];
    const float* fW1  = (const float*)d_in[20];
    const float* fb1  = (const float*)d_in[21];
    const float* fW2  = (const float*)d_in[22];
    const float* fb2  = (const float*)d_in[23];
    float* out = (float*)d_out;

    int *idx0, *idx1, *idx2, *uidx0, *uidx1, *uidx2;
    float *ud20, *ud21, *ud22, *x1, *x2, *x3, *up0, *up1, *wd;
    cudaGetSymbolAddress((void**)&idx0,  g_idx0);
    cudaGetSymbolAddress((void**)&idx1,  g_idx1);
    cudaGetSymbolAddress((void**)&idx2,  g_idx2);
    cudaGetSymbolAddress((void**)&uidx0, g_uidx0);
    cudaGetSymbolAddress((void**)&uidx1, g_uidx1);
    cudaGetSymbolAddress((void**)&uidx2, g_uidx2);
    cudaGetSymbolAddress((void**)&ud20,  g_ud20);
    cudaGetSymbolAddress((void**)&ud21,  g_ud21);
    cudaGetSymbolAddress((void**)&ud22,  g_ud22);
    cudaGetSymbolAddress((void**)&x1,    g_x1);
    cudaGetSymbolAddress((void**)&x2,    g_x2);
    cudaGetSymbolAddress((void**)&x3,    g_x3);
    cudaGetSymbolAddress((void**)&up0,   g_up0);
    cudaGetSymbolAddress((void**)&up1,   g_up1);
    cudaGetSymbolAddress((void**)&wd,    g_wdup);

    const float* d0W1d = wd + 2*OFF_D0W1;
    const float* d0W2d = wd + 2*OFF_D0W2;
    const float* d1W1d = wd + 2*OFF_D1W1;
    const float* d1W2d = wd + 2*OFF_D1W2;
    const float* d2W1d = wd + 2*OFF_D2W1;
    const float* d2W2d = wd + 2*OFF_D2W2;
    const float* u0Wd  = wd + 2*OFF_U0W;
    const float* u1Wd  = wd + 2*OFF_U1W;
    const float* u2Wd  = wd + 2*OFF_U2W;
    const float* fW1d  = wd + 2*OFF_FW1;
    const float* fW2d  = wd + 2*OFF_FW2;

    cudaFuncSetAttribute((const void*)down_kernel<256,512>,
                         cudaFuncAttributeMaxDynamicSharedMemorySize, 56*1024);
    cudaFuncSetAttribute((const void*)up_kernel<512,256,256>,
                         cudaFuncAttributeMaxDynamicSharedMemorySize, 50*1024);

    // ---- weight duplication prep ----
    dup_weights_kernel<<<(W_TOTAL+255)/256, 256>>>(
        d0W1,d0W2,d1W1,d1W2,d2W1,d2W2,u0W,u1W,u2W,fW1,fW2, wd);

    // ---- down 0 ----
    knn_kernel<16,32><<<dim3(NN1,Bz), 256>>>(pos, pos, NN1, NN0, idx0, nullptr);
    down_kernel<3,128><<<dim3(NN1,Bz), 64, (6*16 + 128*16)*sizeof(float)>>>(
        x, pos, idx0, d0W1d,d0b1, d0W2d,d0b2, x1, NN1, NN0*3);
    // ---- down 1 ----
    knn_kernel<16,8><<<dim3(NN2,Bz), 256>>>(pos, pos, NN2, NN1, idx1, nullptr);
    down_kernel<128,256><<<dim3(NN2,Bz), 128, (131*16 + 256*16)*sizeof(float)>>>(
        x1, pos, idx1, d1W1d,d1b1, d1W2d,d1b2, x2, NN2, NN1*128);
    // ---- down 2 ----
    knn_kernel<16,2><<<dim3(NN3,Bz), 256>>>(pos, pos, NN3, NN2, idx2, nullptr);
    down_kernel<256,512><<<dim3(NN3,Bz), 256, (259*16 + 512*16)*sizeof(float)>>>(
        x2, pos, idx2, d2W1d,d2b1, d2W2d,d2b2, x3, NN3, NN2*256);
    // ---- up 0: queries pos2(512) over refs pos3(128) ----
    knn_kernel<3,1><<<dim3(NN2,Bz), 256>>>(pos, pos, NN2, NN3, uidx0, ud20);
    up_kernel<512,256,256><<<dim3(NN2/16,Bz), 128, 768*16*sizeof(float)>>>(
        x3, x2, uidx0, ud20, u0Wd, u0b, up0, NN2, NN3);
    // ---- up 1: queries pos1(2048) over refs pos2(512) ----
    knn_kernel<3,2><<<dim3(NN1,Bz), 256>>>(pos, pos, NN1, NN2, uidx1, ud21);
    up_kernel<256,128,128><<<dim3(NN1/16,Bz), 64, 384*16*sizeof(float)>>>(
        up0, x1, uidx1, ud21, u1Wd, u1b, up1, NN1, NN2);
    // ---- up 2 + final MLP (fused): queries pos0(8192) over refs pos1(2048) ----
    knn_kernel<3,8><<<dim3(NN0,Bz), 256>>>(pos, pos, NN0, NN1, uidx2, ud22);
    up2_final_kernel<<<dim3(NN0/16,Bz), 64>>>(up1, x, pos, uidx2, ud22,
                                              u2Wd,u2b, fW1d,fb1, fW2d,fb2, out);
    // ---- second tuple element: pos0 passthrough ----
    if (out_size >= Bz*NN0*128 + Bz*NN0*3) {
        cudaMemcpyAsync(out + (size_t)Bz*NN0*128, pos,
                        (size_t)Bz*NN0*3*sizeof(float), cudaMemcpyDeviceToDevice);
    }
}